// round 7
// baseline (speedup 1.0000x reference)
#include <cuda_runtime.h>

// Input (B,H,W,C) = (16,128,128,128) fp32, factor (2,2) half-pixel bilinear
// upsample -> (16,256,256,128) fp32.
//
// Quad formulation (R4 body): one work item = (b, qh, qw, c4): 4 float4 tap
// loads -> 4 interior float4 stores (+predicated border stores). This round:
// persistent grid-stride loop so each thread processes ~36 items — the next
// item's independent loads issue right after the current item's stores,
// keeping DRAM queues fed and eliminating CTA wave-transition gaps.

#define B_   16
#define H_   128
#define W_   128
#define C4_  32          // 128 channels / 4
#define OH_  256
#define OW_  256

#define NBLOCKS 912      // ~6 CTAs/SM x 152 SMs
#define NTHREADS 256

__device__ __forceinline__ float4 lerp4(float4 v0, float4 v1, float t) {
    float4 r;
    r.x = fmaf(t, v1.x - v0.x, v0.x);
    r.y = fmaf(t, v1.y - v0.y, v0.y);
    r.z = fmaf(t, v1.z - v0.z, v0.z);
    r.w = fmaf(t, v1.w - v0.w, v0.w);
    return r;
}

__global__ __launch_bounds__(NTHREADS) void upsample2x_quad_gs(
    const float4* __restrict__ in, float4* __restrict__ out)
{
    const int total = B_ * H_ * W_ * C4_;      // 8,388,608 quad items
    const int stride = NBLOCKS * NTHREADS;     // 233,472

    for (int idx = blockIdx.x * NTHREADS + threadIdx.x; idx < total; idx += stride) {
        int c4 = idx & (C4_ - 1);
        int qw = (idx >> 5) & (W_ - 1);
        int qh = (idx >> 12) & (H_ - 1);
        int b  = idx >> 19;

        int r1 = qh < H_ - 1 ? qh + 1 : H_ - 1;
        int c1 = qw < W_ - 1 ? qw + 1 : W_ - 1;

        const float4* base = in + (size_t)b * (H_ * W_ * C4_) + c4;
        float4 v00 = __ldg(base + (qh * W_ + qw) * C4_);
        float4 v01 = __ldg(base + (qh * W_ + c1) * C4_);
        float4 v10 = __ldg(base + (r1 * W_ + qw) * C4_);
        float4 v11 = __ldg(base + (r1 * W_ + c1) * C4_);

        // H interpolation first (matches reference order).
        float4 a0 = lerp4(v00, v10, 0.25f);
        float4 a1 = lerp4(v01, v11, 0.25f);
        float4 b0 = lerp4(v00, v10, 0.75f);
        float4 b1 = lerp4(v01, v11, 0.75f);

        float4* obase = out + (size_t)b * (OH_ * OW_ * C4_) + c4;
        int rowA = 2 * qh + 1;
        int colA = 2 * qw + 1;

        float4* oA = obase + (size_t)rowA * (OW_ * C4_);
        __stcs(oA + colA * C4_, lerp4(a0, a1, 0.25f));
        if (qw < W_ - 1)
            __stcs(oA + (colA + 1) * C4_, lerp4(a0, a1, 0.75f));
        if (qh < H_ - 1) {
            float4* oB = oA + OW_ * C4_;
            __stcs(oB + colA * C4_, lerp4(b0, b1, 0.25f));
            if (qw < W_ - 1)
                __stcs(oB + (colA + 1) * C4_, lerp4(b0, b1, 0.75f));
        }

        // Output row 0 = source row 0 (h-frac collapses), w-interp as usual.
        if (qh == 0) {
            __stcs(obase + colA * C4_, lerp4(v00, v01, 0.25f));
            if (qw < W_ - 1)
                __stcs(obase + (colA + 1) * C4_, lerp4(v00, v01, 0.75f));
            if (qw == 0)
                __stcs(obase, v00);             // (0,0) corner
        }

        // Output col 0 = source col 0 (w-frac collapses): values a0 / b0.
        if (qw == 0) {
            __stcs(obase + (size_t)rowA * (OW_ * C4_), a0);
            if (qh < H_ - 1)
                __stcs(obase + (size_t)(rowA + 1) * (OW_ * C4_), b0);
        }
    }
}

extern "C" void kernel_launch(void* const* d_in, const int* in_sizes, int n_in,
                              void* d_out, int out_size) {
    const float4* in = (const float4*)d_in[0];
    float4* out = (float4*)d_out;
    upsample2x_quad_gs<<<NBLOCKS, NTHREADS>>>(in, out);
}

// round 8
// speedup vs baseline: 1.3077x; 1.3077x over previous
#include <cuda_runtime.h>

// Input (B,H,W,C) = (16,128,128,128) fp32, factor (2,2) half-pixel bilinear
// upsample -> (16,256,256,128) fp32.
//
// R4 quad body, 2 items per thread (batches b and b+8 share the same
// (qh,qw,c4) decode). All 8 tap loads are issued before any compute/store:
// MLP_p1 = 8, double the in-flight load bytes per warp vs R4. One-shot grid
// (no persistent loop — R7 showed loops serialize the DRAM stream).

#define B_   16
#define H_   128
#define W_   128
#define C4_  32          // 128 channels / 4
#define OH_  256
#define OW_  256

__device__ __forceinline__ float4 lerp4(float4 v0, float4 v1, float t) {
    float4 r;
    r.x = fmaf(t, v1.x - v0.x, v0.x);
    r.y = fmaf(t, v1.y - v0.y, v0.y);
    r.z = fmaf(t, v1.z - v0.z, v0.z);
    r.w = fmaf(t, v1.w - v0.w, v0.w);
    return r;
}

__device__ __forceinline__ void emit_quad(
    float4* __restrict__ obase, int rowA, int colA, int qh, int qw,
    float4 v00, float4 v01, float4 v10, float4 v11)
{
    // H interpolation first (matches reference order).
    float4 a0 = lerp4(v00, v10, 0.25f);
    float4 a1 = lerp4(v01, v11, 0.25f);
    float4 b0 = lerp4(v00, v10, 0.75f);
    float4 b1 = lerp4(v01, v11, 0.75f);

    float4* oA = obase + (size_t)rowA * (OW_ * C4_);
    __stcs(oA + colA * C4_, lerp4(a0, a1, 0.25f));
    if (qw < W_ - 1)
        __stcs(oA + (colA + 1) * C4_, lerp4(a0, a1, 0.75f));
    if (qh < H_ - 1) {
        float4* oB = oA + OW_ * C4_;
        __stcs(oB + colA * C4_, lerp4(b0, b1, 0.25f));
        if (qw < W_ - 1)
            __stcs(oB + (colA + 1) * C4_, lerp4(b0, b1, 0.75f));
    }

    // Output row 0 = source row 0 (h-frac collapses), w-interp as usual.
    if (qh == 0) {
        __stcs(obase + colA * C4_, lerp4(v00, v01, 0.25f));
        if (qw < W_ - 1)
            __stcs(obase + (colA + 1) * C4_, lerp4(v00, v01, 0.75f));
        if (qw == 0)
            __stcs(obase, v00);                 // (0,0) corner
    }

    // Output col 0 = source col 0 (w-frac collapses): values a0 / b0.
    if (qw == 0) {
        __stcs(obase + (size_t)rowA * (OW_ * C4_), a0);
        if (qh < H_ - 1)
            __stcs(obase + (size_t)(rowA + 1) * (OW_ * C4_), b0);
    }
}

__global__ __launch_bounds__(256) void upsample2x_quad2(
    const float4* __restrict__ in, float4* __restrict__ out)
{
    int idx = blockIdx.x * 256 + threadIdx.x;   // 8*128*128*32 threads
    int c4 = idx & (C4_ - 1);
    int qw = (idx >> 5) & (W_ - 1);
    int qh = (idx >> 12) & (H_ - 1);
    int b  = idx >> 19;                         // 0..7; pair batch = b+8

    int r1 = qh < H_ - 1 ? qh + 1 : H_ - 1;
    int c1 = qw < W_ - 1 ? qw + 1 : W_ - 1;

    int o00 = (qh * W_ + qw) * C4_;
    int o01 = (qh * W_ + c1) * C4_;
    int o10 = (r1 * W_ + qw) * C4_;
    int o11 = (r1 * W_ + c1) * C4_;

    const float4* baseA = in + (size_t)b * (H_ * W_ * C4_) + c4;
    const float4* baseB = baseA + (size_t)8 * (H_ * W_ * C4_);

    // Front-batched: 8 independent tap loads in flight before any compute.
    float4 A00 = __ldg(baseA + o00);
    float4 A01 = __ldg(baseA + o01);
    float4 A10 = __ldg(baseA + o10);
    float4 A11 = __ldg(baseA + o11);
    float4 B00 = __ldg(baseB + o00);
    float4 B01 = __ldg(baseB + o01);
    float4 B10 = __ldg(baseB + o10);
    float4 B11 = __ldg(baseB + o11);

    int rowA = 2 * qh + 1;
    int colA = 2 * qw + 1;

    float4* obaseA = out + (size_t)b * (OH_ * OW_ * C4_) + c4;
    float4* obaseB = obaseA + (size_t)8 * (OH_ * OW_ * C4_);

    emit_quad(obaseA, rowA, colA, qh, qw, A00, A01, A10, A11);
    emit_quad(obaseB, rowA, colA, qh, qw, B00, B01, B10, B11);
}

extern "C" void kernel_launch(void* const* d_in, const int* in_sizes, int n_in,
                              void* d_out, int out_size) {
    const float4* in = (const float4*)d_in[0];
    float4* out = (float4*)d_out;
    int total = 8 * H_ * W_ * C4_;     // 4,194,304 threads (half the items, x2 each)
    upsample2x_quad2<<<total / 256, 256>>>(in, out);
}

// round 10
// speedup vs baseline: 1.3481x; 1.0309x over previous
#include <cuda_runtime.h>

// Input (B,H,W,C) = (16,128,128,128) fp32, factor (2,2) half-pixel bilinear
// upsample -> (16,256,256,128) fp32.
//
// R4 quad body (best measured: 6.37 TB/s, traffic at the 640MB floor), tuned:
// block=128 for finer CTA scheduling granularity (smaller wave-tail quantum,
// smaller per-CTA L1tex load burst), exact grid (no bounds check).
// One work item per thread: (b,qh,qw,c4) -> 4 tap loads, 4+ stores.

#define B_   16
#define H_   128
#define W_   128
#define C4_  32          // 128 channels / 4
#define OH_  256
#define OW_  256

#define NT_  128

__device__ __forceinline__ float4 lerp4(float4 v0, float4 v1, float t) {
    float4 r;
    r.x = fmaf(t, v1.x - v0.x, v0.x);
    r.y = fmaf(t, v1.y - v0.y, v0.y);
    r.z = fmaf(t, v1.z - v0.z, v0.z);
    r.w = fmaf(t, v1.w - v0.w, v0.w);
    return r;
}

__global__ __launch_bounds__(NT_) void upsample2x_quad_b128(
    const float4* __restrict__ in, float4* __restrict__ out)
{
    int idx = blockIdx.x * NT_ + threadIdx.x;   // exactly B*128*128*32 threads
    int c4 = idx & (C4_ - 1);
    int qw = (idx >> 5) & (W_ - 1);
    int qh = (idx >> 12) & (H_ - 1);
    int b  = idx >> 19;

    int r1 = qh < H_ - 1 ? qh + 1 : H_ - 1;
    int c1 = qw < W_ - 1 ? qw + 1 : W_ - 1;

    const float4* base = in + (size_t)b * (H_ * W_ * C4_) + c4;
    float4 v00 = __ldg(base + (qh * W_ + qw) * C4_);
    float4 v01 = __ldg(base + (qh * W_ + c1) * C4_);
    float4 v10 = __ldg(base + (r1 * W_ + qw) * C4_);
    float4 v11 = __ldg(base + (r1 * W_ + c1) * C4_);

    // H interpolation first (matches reference order).
    float4 a0 = lerp4(v00, v10, 0.25f);
    float4 a1 = lerp4(v01, v11, 0.25f);
    float4 b0 = lerp4(v00, v10, 0.75f);
    float4 b1 = lerp4(v01, v11, 0.75f);

    float4* obase = out + (size_t)b * (OH_ * OW_ * C4_) + c4;
    int rowA = 2 * qh + 1;
    int colA = 2 * qw + 1;

    float4* oA = obase + (size_t)rowA * (OW_ * C4_);
    __stcs(oA + colA * C4_, lerp4(a0, a1, 0.25f));
    if (qw < W_ - 1)
        __stcs(oA + (colA + 1) * C4_, lerp4(a0, a1, 0.75f));
    if (qh < H_ - 1) {
        float4* oB = oA + OW_ * C4_;
        __stcs(oB + colA * C4_, lerp4(b0, b1, 0.25f));
        if (qw < W_ - 1)
            __stcs(oB + (colA + 1) * C4_, lerp4(b0, b1, 0.75f));
    }

    // Output row 0 = source row 0 (h-frac collapses), w-interp as usual.
    if (qh == 0) {
        __stcs(obase + colA * C4_, lerp4(v00, v01, 0.25f));
        if (qw < W_ - 1)
            __stcs(obase + (colA + 1) * C4_, lerp4(v00, v01, 0.75f));
        if (qw == 0)
            __stcs(obase, v00);                 // (0,0) corner
    }

    // Output col 0 = source col 0 (w-frac collapses): values a0 / b0.
    if (qw == 0) {
        __stcs(obase + (size_t)rowA * (OW_ * C4_), a0);
        if (qh < H_ - 1)
            __stcs(obase + (size_t)(rowA + 1) * (OW_ * C4_), b0);
    }
}

extern "C" void kernel_launch(void* const* d_in, const int* in_sizes, int n_in,
                              void* d_out, int out_size) {
    const float4* in = (const float4*)d_in[0];
    float4* out = (float4*)d_out;
    int total = B_ * H_ * W_ * C4_;    // 8,388,608 threads
    upsample2x_quad_b128<<<total / NT_, NT_>>>(in, out);
}